// round 9
// baseline (speedup 1.0000x reference)
#include <cuda_runtime.h>

// SSIM loss: X,Y (4,64,256,256) fp32, 7x7 valid box, loss scalar -> out[4].
// loss = 1 - mean(S) over all (B*D, 250, 250) pixels.
//
// Scale-folded formula (49^4 cancels): with H* = raw 7x7 window sums and
// Hxy2 = 2*Hxy (doubled cross-sum is tracked):
//   A1 = 2*Hx*Hy + c1                    c1 = 49^2*1e-4
//   A2 = 49c*Hxy2 - 2c*Hx*Hy + c2        c2 = 49^2*9e-4,  c = 49/48
//   B1 = Hx^2 + Hy^2 + c1
//   B2 = c*(49*Hq - Hx^2 - Hy^2) + c2    (Hq = window sum of x^2+y^2)
//   S  = A1*A2 / (B1*B2)
//
// Lane owns cols [8L,8L+8). Entering rows prefetched one iteration ahead
// (DRAM latency); leaving rows loaded mid-body (L1/L2 hit, hidden by the
// epilogue). Grid sized to the register-file occupancy limit (~21 warps/SM).

#define WIN 7
#define HH 256
#define WW 256
#define NSLICES 256
#define BANDS 12             // 11 bands of 21 rows + 1 of 19 = 250
#define RPB 21
#define NCTA (NSLICES * BANDS)   // 3072 single-warp CTAs = 20.8/SM
#define NSLOT 64
#define NPIX 16000000.0

__device__ double   g_slots[NSLOT];
__device__ unsigned g_ticket = 0;

typedef unsigned long long u64;

__device__ __forceinline__ u64 pk(float lo, float hi) {
    u64 r; asm("mov.b64 %0, {%1,%2};" : "=l"(r) : "f"(lo), "f"(hi)); return r;
}
__device__ __forceinline__ void upk(u64 v, float& lo, float& hi) {
    asm("mov.b64 {%0,%1}, %2;" : "=f"(lo), "=f"(hi) : "l"(v));
}
__device__ __forceinline__ u64 f2add(u64 a, u64 b) {
    u64 d; asm("add.rn.f32x2 %0,%1,%2;" : "=l"(d) : "l"(a), "l"(b)); return d;
}
__device__ __forceinline__ u64 f2sub(u64 a, u64 b) {
    u64 d; asm("sub.rn.f32x2 %0,%1,%2;" : "=l"(d) : "l"(a), "l"(b)); return d;
}
__device__ __forceinline__ u64 f2mul(u64 a, u64 b) {
    u64 d; asm("mul.rn.f32x2 %0,%1,%2;" : "=l"(d) : "l"(a), "l"(b)); return d;
}
__device__ __forceinline__ u64 f2fma(u64 a, u64 b, u64 c) {
    u64 d; asm("fma.rn.f32x2 %0,%1,%2,%3;" : "=l"(d) : "l"(a), "l"(b), "l"(c)); return d;
}

// Horizontal 7-window sums. Own prefix (7-deep chain) + neighbor prefix
// pairs via SHFL:  W(j..j+6) = P7 + Q[j-2] - P[j-1]; W0=P6; W1=P7-P0.
// Lane 31's W[1..3] are garbage (masked by caller).
__device__ __forceinline__ void horiz(const u64 F[4], u64 W[4]) {
    float s0, s1, s2, s3, s4, s5, s6, s7;
    upk(F[0], s0, s1); upk(F[1], s2, s3);
    upk(F[2], s4, s5); upk(F[3], s6, s7);
    float P0 = s0, P1 = P0 + s1, P2 = P1 + s2, P3 = P2 + s3;
    float P4 = P3 + s4, P5 = P4 + s5, P6 = P5 + s6, P7 = P6 + s7;
    u64 A01 = pk(P0, P1), A23 = pk(P2, P3), A45 = pk(P4, P5);
    u64 Q01 = __shfl_down_sync(0xFFFFFFFFu, A01, 1);
    u64 Q23 = __shfl_down_sync(0xFFFFFFFFu, A23, 1);
    u64 Q45 = __shfl_down_sync(0xFFFFFFFFu, A45, 1);
    u64 P77 = pk(P7, P7);
    W[0] = f2sub(pk(P6, P7), pk(0.0f, P0));
    W[1] = f2add(P77, f2sub(Q01, pk(P1, P2)));
    W[2] = f2add(P77, f2sub(Q23, pk(P3, P4)));
    W[3] = f2add(P77, f2sub(Q45, pk(P5, P6)));
}

__global__ void __launch_bounds__(32, 21) ssim_main_kernel(
        const float* __restrict__ X, const float* __restrict__ Y,
        float* __restrict__ out, int out_size) {
    const int b     = blockIdx.x;
    const int lane  = threadIdx.x;
    const int slice = b / BANDS;
    const int band  = b % BANDS;

    // Row stride = 64 ulonglong2 (256 floats); lane offset = 2 (8 floats).
    const ulonglong2* xr = (const ulonglong2*)(X + (size_t)slice * (HH * WW)) + lane * 2;
    const ulonglong2* yr = (const ulonglong2*)(Y + (size_t)slice * (HH * WW)) + lane * 2;

    const float covn = 49.0f / 48.0f;
    const u64 C1V   = pk(0.2401f, 0.2401f);
    const u64 C2V   = pk(2.1609f, 2.1609f);
    const u64 TWOV  = pk(2.0f, 2.0f);
    const u64 NCV2  = pk(-2.0f * covn, -2.0f * covn);
    const u64 NCV   = pk(-covn, -covn);
    const u64 CV_49 = pk(49.0f * covn, 49.0f * covn);
    const u64 edgemask = (lane == 31) ? pk(0.0f, 0.0f) : pk(1.0f, 1.0f);

    u64 sx2[4], sy2[4], sq2[4], sxy2[4];   // sxy2 tracks 2*sum(x*y)
#pragma unroll
    for (int p = 0; p < 4; p++) {
        sx2[p] = pk(0.f, 0.f); sy2[p] = pk(0.f, 0.f);
        sq2[p] = pk(0.f, 0.f); sxy2[p] = pk(0.f, 0.f);
    }

    const int r0    = band * RPB;
    const int nrows = (250 - r0 < RPB) ? (250 - r0) : RPB;   // last band: 19

    // Prologue: full first window, rows r0 .. r0+6.
    for (int r = r0; r < r0 + WIN; ++r) {
        ulonglong2 xa = xr[r * 64], xb = xr[r * 64 + 1];
        ulonglong2 ya = yr[r * 64], yb = yr[r * 64 + 1];
        u64 xv[4] = {xa.x, xa.y, xb.x, xb.y};
        u64 yv[4] = {ya.x, ya.y, yb.x, yb.y};
#pragma unroll
        for (int p = 0; p < 4; p++) {
            sx2[p]  = f2add(sx2[p], xv[p]);
            sy2[p]  = f2add(sy2[p], yv[p]);
            sq2[p]  = f2fma(xv[p], xv[p], sq2[p]);
            sq2[p]  = f2fma(yv[p], yv[p], sq2[p]);
            u64 x2  = f2add(xv[p], xv[p]);
            sxy2[p] = f2fma(x2, yv[p], sxy2[p]);   // += 2*x*y
        }
    }

    // Prefetch entering row r0+7 only (DRAM-latency critical).
    ulonglong2 nxa = xr[(r0 + 7) * 64], nxb = xr[(r0 + 7) * 64 + 1];
    ulonglong2 nya = yr[(r0 + 7) * 64], nyb = yr[(r0 + 7) * 64 + 1];

    u64 acc2 = pk(0.f, 0.f);

    for (int i = r0; i < r0 + nrows; ++i) {
        // ---- Emit outputs for window(i) (state = rows i..i+6) ----
        u64 Wx[4], Wy[4], Wq[4], Wxy[4];
        horiz(sx2,  Wx);
        horiz(sy2,  Wy);
        horiz(sq2,  Wq);
        horiz(sxy2, Wxy);

        // Leaving row i: L1/L2 hit; latency hidden by the epilogue below.
        ulonglong2 oxa = xr[i * 64], oxb = xr[i * 64 + 1];
        ulonglong2 oya = yr[i * 64], oyb = yr[i * 64 + 1];

        u64 num[4], den[4];
#pragma unroll
        for (int m = 0; m < 4; m++) {
            u64 Hx = Wx[m], Hy = Wy[m], Hq = Wq[m], Hxy2 = Wxy[m];
            u64 Pp = f2mul(Hx, Hy);
            u64 A1 = f2fma(TWOV,  Pp,   C1V);
            u64 T  = f2fma(NCV2,  Pp,   C2V);
            u64 A2 = f2fma(CV_49, Hxy2, T);        // 49c*(2Hxy) - 2c*P + c2
            u64 S2 = f2fma(Hx, Hx, f2mul(Hy, Hy));
            u64 B1 = f2add(S2, C1V);
            u64 U  = f2fma(NCV,   S2, C2V);
            u64 B2 = f2fma(CV_49, Hq, U);
            u64 N  = f2mul(A1, A2);
            if (m > 0) N = f2mul(N, edgemask);
            num[m] = N;
            den[m] = f2mul(B1, B2);                // > 0 always
        }
        // Merge 4 packed fractions -> one reciprocal per row.
        u64 na = f2fma(num[1], den[0], f2mul(num[0], den[1]));
        u64 da = f2mul(den[0], den[1]);
        u64 nb = f2fma(num[3], den[2], f2mul(num[2], den[3]));
        u64 db = f2mul(den[2], den[3]);
        u64 N  = f2fma(nb, da, f2mul(na, db));
        u64 D  = f2mul(da, db);

        float dl, dh; upk(D, dl, dh);
        u64 r = pk(__uint_as_float(0x7EF311C3u - __float_as_uint(dl)),
                   __uint_as_float(0x7EF311C3u - __float_as_uint(dh)));
        u64 ndv = D ^ 0x8000000080000000ULL;       // -D on the ALU pipe
        u64 t = f2fma(ndv, r, TWOV); r = f2mul(r, t);
        t     = f2fma(ndv, r, TWOV); r = f2mul(r, t);
        acc2  = f2fma(N, r, acc2);

        // ---- Advance to window(i+1) ----
        u64 xn[4] = {nxa.x, nxa.y, nxb.x, nxb.y};
        u64 yn[4] = {nya.x, nya.y, nyb.x, nyb.y};
        u64 xo[4] = {oxa.x, oxa.y, oxb.x, oxb.y};
        u64 yo[4] = {oya.x, oya.y, oyb.x, oyb.y};

        // Delta update: x_n^2-x_o^2 = dx*(x_n+x_o);
        // 2(x_n y_n - x_o y_o) = dx*(y_n+y_o) + dy*(x_n+x_o)
#pragma unroll
        for (int p = 0; p < 4; p++) {
            u64 dx  = f2sub(xn[p], xo[p]), sxp = f2add(xn[p], xo[p]);
            u64 dy  = f2sub(yn[p], yo[p]), syp = f2add(yn[p], yo[p]);
            sx2[p]  = f2add(sx2[p], dx);
            sy2[p]  = f2add(sy2[p], dy);
            sq2[p]  = f2fma(dx, sxp, sq2[p]);
            sq2[p]  = f2fma(dy, syp, sq2[p]);
            sxy2[p] = f2fma(dx, syp, sxy2[p]);
            sxy2[p] = f2fma(dy, sxp, sxy2[p]);
        }

        // Prefetch entering row for next iteration (row i+8, clamped).
        int nr = i + 8; if (nr > HH - 1) nr = HH - 1;
        nxa = xr[nr * 64]; nxb = xr[nr * 64 + 1];
        nya = yr[nr * 64]; nyb = yr[nr * 64 + 1];
    }

    // Warp reduce -> one double atomic per CTA, spread over 64 slots.
    float al, ah; upk(acc2, al, ah);
    float acc = al + ah;
#pragma unroll
    for (int o = 16; o > 0; o >>= 1)
        acc += __shfl_down_sync(0xFFFFFFFFu, acc, o);
    if (lane == 0)
        atomicAdd(&g_slots[b & (NSLOT - 1)], (double)acc);

    // ---- Fused finalize: last CTA computes loss and writes out ----
    __threadfence();
    unsigned ticket = 0xFFFFFFFFu;
    if (lane == 0) ticket = atomicInc(&g_ticket, 0xFFFFFFFFu);
    ticket = __shfl_sync(0xFFFFFFFFu, ticket, 0);
    if (ticket == NCTA - 1) {
        __threadfence();
        double v = g_slots[lane] + g_slots[lane + 32];
        g_slots[lane] = 0.0;
        g_slots[lane + 32] = 0.0;
#pragma unroll
        for (int o = 16; o > 0; o >>= 1)
            v += __shfl_down_sync(0xFFFFFFFFu, v, o);
        if (lane == 0) {
            float loss = (float)(1.0 - v * (1.0 / NPIX));
            for (int k = 0; k < out_size; k++) out[k] = loss;
            g_ticket = 0;
        }
    }
}

extern "C" void kernel_launch(void* const* d_in, const int* in_sizes, int n_in,
                              void* d_out, int out_size) {
    const float* X = nullptr;
    const float* Y = nullptr;
    for (int i = 0; i < n_in; i++) {
        if (in_sizes[i] == 4 * 64 * 256 * 256) {
            if (!X) X = (const float*)d_in[i];
            else if (!Y) Y = (const float*)d_in[i];
        }
    }
    ssim_main_kernel<<<NCTA, 32>>>(X, Y, (float*)d_out, out_size);
}

// round 10
// speedup vs baseline: 1.6455x; 1.6455x over previous
#include <cuda_runtime.h>

// SSIM loss: X,Y (4,64,256,256) fp32, 7x7 valid box, loss scalar -> out[4].
// loss = 1 - mean(S) over all (B*D, 250, 250) pixels.
//
// Scale-folded formula (49^4 cancels): with H* = raw 7x7 window sums and
// Hxy2 = 2*Hxy (doubled cross-sum tracked):
//   A1 = 2*Hx*Hy + c1                    c1 = 49^2*1e-4
//   A2 = 49c*Hxy2 - 2c*Hx*Hy + c2        c2 = 49^2*9e-4,  c = 49/48
//   B1 = Hx^2 + Hy^2 + c1
//   B2 = c*(49*Hq - Hx^2 - Hy^2) + c2    (Hq = window sum of x^2+y^2)
//   S  = A1*A2 / (B1*B2)
//
// R6 chassis (proven fastest): BANDS=9, lb(32,16) -> 128 regs no spill,
// BOTH entering and leaving rows prefetched a full iteration ahead.

#define WIN 7
#define HH 256
#define WW 256
#define NSLICES 256
#define BANDS 9              // 8 bands of 28 rows + 1 of 26 = 250
#define RPBMAX 28
#define NCTA (NSLICES * BANDS)   // 2304 single-warp CTAs: one wave @16/SM
#define NSLOT 64
#define NPIX 16000000.0

__device__ double   g_slots[NSLOT];
__device__ unsigned g_ticket = 0;

typedef unsigned long long u64;

__device__ __forceinline__ u64 pk(float lo, float hi) {
    u64 r; asm("mov.b64 %0, {%1,%2};" : "=l"(r) : "f"(lo), "f"(hi)); return r;
}
__device__ __forceinline__ void upk(u64 v, float& lo, float& hi) {
    asm("mov.b64 {%0,%1}, %2;" : "=f"(lo), "=f"(hi) : "l"(v));
}
__device__ __forceinline__ u64 f2add(u64 a, u64 b) {
    u64 d; asm("add.rn.f32x2 %0,%1,%2;" : "=l"(d) : "l"(a), "l"(b)); return d;
}
__device__ __forceinline__ u64 f2sub(u64 a, u64 b) {
    u64 d; asm("sub.rn.f32x2 %0,%1,%2;" : "=l"(d) : "l"(a), "l"(b)); return d;
}
__device__ __forceinline__ u64 f2mul(u64 a, u64 b) {
    u64 d; asm("mul.rn.f32x2 %0,%1,%2;" : "=l"(d) : "l"(a), "l"(b)); return d;
}
__device__ __forceinline__ u64 f2fma(u64 a, u64 b, u64 c) {
    u64 d; asm("fma.rn.f32x2 %0,%1,%2,%3;" : "=l"(d) : "l"(a), "l"(b), "l"(c)); return d;
}

// Horizontal 7-window sums. Own prefix (7-deep chain) + neighbor prefix
// pairs via SHFL:  W(j..j+6) = P7 + Q[j-2] - P[j-1]; W0=P6; W1=P7-P0.
// Lane 31's W[1..3] are garbage (masked by caller).
__device__ __forceinline__ void horiz(const u64 F[4], u64 W[4]) {
    float s0, s1, s2, s3, s4, s5, s6, s7;
    upk(F[0], s0, s1); upk(F[1], s2, s3);
    upk(F[2], s4, s5); upk(F[3], s6, s7);
    float P0 = s0, P1 = P0 + s1, P2 = P1 + s2, P3 = P2 + s3;
    float P4 = P3 + s4, P5 = P4 + s5, P6 = P5 + s6, P7 = P6 + s7;
    u64 A01 = pk(P0, P1), A23 = pk(P2, P3), A45 = pk(P4, P5);
    u64 Q01 = __shfl_down_sync(0xFFFFFFFFu, A01, 1);
    u64 Q23 = __shfl_down_sync(0xFFFFFFFFu, A23, 1);
    u64 Q45 = __shfl_down_sync(0xFFFFFFFFu, A45, 1);
    u64 P77 = pk(P7, P7);
    W[0] = f2sub(pk(P6, P7), pk(0.0f, P0));
    W[1] = f2add(P77, f2sub(Q01, pk(P1, P2)));
    W[2] = f2add(P77, f2sub(Q23, pk(P3, P4)));
    W[3] = f2add(P77, f2sub(Q45, pk(P5, P6)));
}

__global__ void __launch_bounds__(32, 16) ssim_main_kernel(
        const float* __restrict__ X, const float* __restrict__ Y,
        float* __restrict__ out, int out_size) {
    const int b     = blockIdx.x;
    const int lane  = threadIdx.x;
    const int slice = b / BANDS;
    const int band  = b % BANDS;

    // Row stride = 64 ulonglong2 (256 floats); lane offset = 2 (8 floats).
    const ulonglong2* xr = (const ulonglong2*)(X + (size_t)slice * (HH * WW)) + lane * 2;
    const ulonglong2* yr = (const ulonglong2*)(Y + (size_t)slice * (HH * WW)) + lane * 2;

    const float covn = 49.0f / 48.0f;
    const u64 C1V   = pk(0.2401f, 0.2401f);
    const u64 C2V   = pk(2.1609f, 2.1609f);
    const u64 TWOV  = pk(2.0f, 2.0f);
    const u64 NCV2  = pk(-2.0f * covn, -2.0f * covn);
    const u64 NCV   = pk(-covn, -covn);
    const u64 CV_49 = pk(49.0f * covn, 49.0f * covn);
    const u64 edgemask = (lane == 31) ? pk(0.0f, 0.0f) : pk(1.0f, 1.0f);

    u64 sx2[4], sy2[4], sq2[4], sxy2[4];   // sxy2 tracks 2*sum(x*y)
#pragma unroll
    for (int p = 0; p < 4; p++) {
        sx2[p] = pk(0.f, 0.f); sy2[p] = pk(0.f, 0.f);
        sq2[p] = pk(0.f, 0.f); sxy2[p] = pk(0.f, 0.f);
    }

    const int r0    = band * RPBMAX;
    const int nrows = (250 - r0 < RPBMAX) ? (250 - r0) : RPBMAX;

    // Prologue: full first window, rows r0 .. r0+6.
    for (int r = r0; r < r0 + WIN; ++r) {
        ulonglong2 xa = xr[r * 64], xb = xr[r * 64 + 1];
        ulonglong2 ya = yr[r * 64], yb = yr[r * 64 + 1];
        u64 xv[4] = {xa.x, xa.y, xb.x, xb.y};
        u64 yv[4] = {ya.x, ya.y, yb.x, yb.y};
#pragma unroll
        for (int p = 0; p < 4; p++) {
            sx2[p]  = f2add(sx2[p], xv[p]);
            sy2[p]  = f2add(sy2[p], yv[p]);
            sq2[p]  = f2fma(xv[p], xv[p], sq2[p]);
            sq2[p]  = f2fma(yv[p], yv[p], sq2[p]);
            u64 x2  = f2add(xv[p], xv[p]);
            sxy2[p] = f2fma(x2, yv[p], sxy2[p]);   // += 2*x*y
        }
    }

    // Prefetch BOTH rows a full iteration ahead (R6 pattern):
    // entering row r0+7 (DRAM) and leaving row r0 (L1/L2).
    ulonglong2 nxa = xr[(r0 + 7) * 64], nxb = xr[(r0 + 7) * 64 + 1];
    ulonglong2 nya = yr[(r0 + 7) * 64], nyb = yr[(r0 + 7) * 64 + 1];
    ulonglong2 oxa = xr[r0 * 64],       oxb = xr[r0 * 64 + 1];
    ulonglong2 oya = yr[r0 * 64],       oyb = yr[r0 * 64 + 1];

    u64 acc2 = pk(0.f, 0.f);

    for (int i = r0; i < r0 + nrows; ++i) {
        // ---- Emit outputs for window(i) (state = rows i..i+6) ----
        u64 Wx[4], Wy[4], Wq[4], Wxy[4];
        horiz(sx2,  Wx);
        horiz(sy2,  Wy);
        horiz(sq2,  Wq);
        horiz(sxy2, Wxy);

        u64 num[4], den[4];
#pragma unroll
        for (int m = 0; m < 4; m++) {
            u64 Hx = Wx[m], Hy = Wy[m], Hq = Wq[m], Hxy2 = Wxy[m];
            u64 Pp = f2mul(Hx, Hy);
            u64 A1 = f2fma(TWOV,  Pp,   C1V);
            u64 T  = f2fma(NCV2,  Pp,   C2V);
            u64 A2 = f2fma(CV_49, Hxy2, T);        // 49c*(2Hxy) - 2c*P + c2
            u64 S2 = f2fma(Hx, Hx, f2mul(Hy, Hy));
            u64 B1 = f2add(S2, C1V);
            u64 U  = f2fma(NCV,   S2, C2V);
            u64 B2 = f2fma(CV_49, Hq, U);
            u64 N  = f2mul(A1, A2);
            if (m > 0) N = f2mul(N, edgemask);
            num[m] = N;
            den[m] = f2mul(B1, B2);                // > 0 always
        }
        // Merge 4 packed fractions -> one reciprocal per row.
        u64 na = f2fma(num[1], den[0], f2mul(num[0], den[1]));
        u64 da = f2mul(den[0], den[1]);
        u64 nb = f2fma(num[3], den[2], f2mul(num[2], den[3]));
        u64 db = f2mul(den[2], den[3]);
        u64 N  = f2fma(nb, da, f2mul(na, db));
        u64 D  = f2mul(da, db);

        float dl, dh; upk(D, dl, dh);
        u64 r = pk(__uint_as_float(0x7EF311C3u - __float_as_uint(dl)),
                   __uint_as_float(0x7EF311C3u - __float_as_uint(dh)));
        u64 ndv = D ^ 0x8000000080000000ULL;       // -D on the ALU pipe
        u64 t = f2fma(ndv, r, TWOV); r = f2mul(r, t);
        t     = f2fma(ndv, r, TWOV); r = f2mul(r, t);
        acc2  = f2fma(N, r, acc2);

        // ---- Advance to window(i+1) with prefetched rows ----
        u64 xn[4] = {nxa.x, nxa.y, nxb.x, nxb.y};
        u64 yn[4] = {nya.x, nya.y, nyb.x, nyb.y};
        u64 xo[4] = {oxa.x, oxa.y, oxb.x, oxb.y};
        u64 yo[4] = {oya.x, oya.y, oyb.x, oyb.y};

        // Prefetch for next iteration: entering row i+8 (clamped), leaving i+1.
        int nr = i + 8; if (nr > HH - 1) nr = HH - 1;
        nxa = xr[nr * 64];       nxb = xr[nr * 64 + 1];
        nya = yr[nr * 64];       nyb = yr[nr * 64 + 1];
        oxa = xr[(i + 1) * 64];  oxb = xr[(i + 1) * 64 + 1];
        oya = yr[(i + 1) * 64];  oyb = yr[(i + 1) * 64 + 1];

        // Delta update: x_n^2-x_o^2 = dx*(x_n+x_o);
        // 2(x_n y_n - x_o y_o) = dx*(y_n+y_o) + dy*(x_n+x_o)
#pragma unroll
        for (int p = 0; p < 4; p++) {
            u64 dx  = f2sub(xn[p], xo[p]), sxp = f2add(xn[p], xo[p]);
            u64 dy  = f2sub(yn[p], yo[p]), syp = f2add(yn[p], yo[p]);
            sx2[p]  = f2add(sx2[p], dx);
            sy2[p]  = f2add(sy2[p], dy);
            sq2[p]  = f2fma(dx, sxp, sq2[p]);
            sq2[p]  = f2fma(dy, syp, sq2[p]);
            sxy2[p] = f2fma(dx, syp, sxy2[p]);
            sxy2[p] = f2fma(dy, sxp, sxy2[p]);
        }
    }

    // Warp reduce -> one double atomic per CTA, spread over 64 slots.
    float al, ah; upk(acc2, al, ah);
    float acc = al + ah;
#pragma unroll
    for (int o = 16; o > 0; o >>= 1)
        acc += __shfl_down_sync(0xFFFFFFFFu, acc, o);
    if (lane == 0)
        atomicAdd(&g_slots[b & (NSLOT - 1)], (double)acc);

    // ---- Fused finalize: last CTA computes loss and writes out ----
    __threadfence();
    unsigned ticket = 0xFFFFFFFFu;
    if (lane == 0) ticket = atomicInc(&g_ticket, 0xFFFFFFFFu);
    ticket = __shfl_sync(0xFFFFFFFFu, ticket, 0);
    if (ticket == NCTA - 1) {
        __threadfence();
        double v = g_slots[lane] + g_slots[lane + 32];
        g_slots[lane] = 0.0;
        g_slots[lane + 32] = 0.0;
#pragma unroll
        for (int o = 16; o > 0; o >>= 1)
            v += __shfl_down_sync(0xFFFFFFFFu, v, o);
        if (lane == 0) {
            float loss = (float)(1.0 - v * (1.0 / NPIX));
            for (int k = 0; k < out_size; k++) out[k] = loss;
            g_ticket = 0;
        }
    }
}

extern "C" void kernel_launch(void* const* d_in, const int* in_sizes, int n_in,
                              void* d_out, int out_size) {
    const float* X = nullptr;
    const float* Y = nullptr;
    for (int i = 0; i < n_in; i++) {
        if (in_sizes[i] == 4 * 64 * 256 * 256) {
            if (!X) X = (const float*)d_in[i];
            else if (!Y) Y = (const float*)d_in[i];
        }
    }
    ssim_main_kernel<<<NCTA, 32>>>(X, Y, (float*)d_out, out_size);
}